// round 6
// baseline (speedup 1.0000x reference)
#include <cuda_runtime.h>
#include <math.h>

#define NN 256
#define BB 1024
#define NJOB 1025
#define NB 32
#define NPAN 8
#define STRP 256
#define STRU 224

typedef unsigned long long ull;

// ---- device globals (no allocation allowed anywhere) ----
__device__ float4 g_T[NN * NN];                  // 1 MB: T[i][j][{00,01,10,11}]
__device__ float  g_Ws[NN * NN];                 // symmetric sigmoid(W), zero diag
__device__ float2 g_logV[NN];                    // log V[j,0], log V[j,1]
__device__ float  g_A[(size_t)NJOB * NN * NN];   // 268.7 MB LU scratch
__device__ float  g_ld[NJOB];
__device__ float  g_logPr[NJOB];
__device__ int    g_dummy;

__device__ __forceinline__ float sigm(float z) { return 1.0f / (1.0f + expf(-z)); }
__device__ __forceinline__ float clip01(float v) { return fminf(fmaxf(v, 0.0f), 1.0f); }

// ---- packed f32x2 helpers (FFMA2 only reachable via PTX on sm_103a) ----
__device__ __forceinline__ ull splat2(float x) {
    ull r;
    asm("mov.b64 %0, {%1, %1};" : "=l"(r) : "f"(x));
    return r;
}
__device__ __forceinline__ void ffma2(ull& d, ull a, ull b) {
    asm("fma.rn.f32x2 %0, %1, %2, %0;" : "+l"(d) : "l"(a), "l"(b));
}

__global__ void dummy_kernel() {
    if (threadIdx.x == 0) g_dummy = blockIdx.x;
}

// ============================================================================
// Kernel 1: batch-independent precompute of T, Ws, logV
// ============================================================================
__global__ void precompute_kernel(const float* __restrict__ W,
                                  const float* __restrict__ lam,
                                  const float* __restrict__ Vc) {
    int i = blockIdx.x, j = threadIdx.x;
    float vi0 = sigm(Vc[2 * i]), vi1 = sigm(Vc[2 * i + 1]);
    float si = vi0 + vi1; vi0 /= si; vi1 /= si;
    float vj0 = sigm(Vc[2 * j]), vj1 = sigm(Vc[2 * j + 1]);
    float sj = vj0 + vj1; vj0 /= sj; vj1 /= sj;

    float ws;
    if (i > j)      ws = sigm(W[i * NN + j]);
    else if (i < j) ws = sigm(W[j * NN + i]);
    else            ws = 0.0f;
    g_Ws[i * NN + j] = ws;

    float t00 = 0.f, t01 = 0.f, t10 = 0.f, t11 = 0.f;
    if (i != j) {
        float lower = fmaxf(1e-7f, vi0 + vj0 - 1.0f);
        float upper = fminf(vi0, vj0);
        float sg = sigm(lam[i * NN + j]);
        float P00 = lower + sg * (upper - lower);
        float P01 = vi0 - P00;
        float P10 = vj0 - P00;
        float P11 = 1.0f - vi0 - vj0 + P00;
        P00 = clip01(P00); P01 = clip01(P01); P10 = clip01(P10); P11 = clip01(P11);
        t00 = ws * P00 / (vi0 * vj0);
        t01 = ws * P01 / (vi0 * vj1);
        t10 = ws * P10 / (vi1 * vj0);
        t11 = ws * P11 / (vi1 * vj1);
    }
    g_T[i * NN + j] = make_float4(t00, t01, t10, t11);
    if (i == 0) g_logV[j] = make_float2(logf(vj0), logf(vj1));
}

// ============================================================================
// Kernel 2: one CTA per job, 3 CTAs/SM. Blocked no-pivot LU, NB=32.
// ============================================================================
#define SMEM_WORDS (NB * STRP + NB * STRU + 64 + 8 + 8 + 256)
#define SMEM_BYTES (SMEM_WORDS * 4)

extern __shared__ float smem[];

__global__ void __launch_bounds__(256, 3) lu_kernel(const int* __restrict__ x) {
    const int job  = blockIdx.x;
    const int tid  = threadIdx.x;
    const int lane = tid & 31;
    const int wid  = tid >> 5;
    const bool isL0 = (job == NJOB - 1);

    float* sP  = smem;                 // NB cols x STRP rows, col-major NEGATED panel
    float* sU  = sP + NB * STRP;       // NB rows x STRU, row-major U12
    float* sB  = sU + NB * STRU;       // 2 x 32 double-buffered pivot row
    float* sW  = sB + 64;              // 8 per-warp logPr partials
    float* sLd = sW + 8;               // 8 per-panel pivot-log sums
    int*   xs  = (int*)(sLd + 8);      // 256 labels

    float* __restrict__ A = g_A + (size_t)job * (NN * NN);

    if (!isL0) xs[tid] = x[job * NN + tid];
    __syncthreads();

    // ---- logPr[b] = sum_i log V[i, x[b,i]] ----
    if (!isL0) {
        float2 lv2 = g_logV[tid];
        float lv = xs[tid] ? lv2.y : lv2.x;
#pragma unroll
        for (int o = 16; o; o >>= 1) lv += __shfl_xor_sync(0xffffffffu, lv, o);
        if (lane == 0) sW[wid] = lv;
    }

    // ---- build M into A: rows/cols 0..254 = nodes 1..255; 255 = pad ----
    for (int io = wid; io < NN; io += 8) {
        if (io == 255) {
#pragma unroll
            for (int c = 0; c < 8; c++) {
                int j = c * 32 + lane;
                A[255 * NN + j] = (j == 255) ? 1.0f : 0.0f;
            }
        } else {
            int i = io + 1;
            float acc = 0.0f;
            if (!isL0) {
                int xi = xs[i];
#pragma unroll
                for (int c = 0; c < 8; c++) {
                    int j = c * 32 + lane;
                    float4 t = g_T[i * NN + j];
                    int xj = xs[j];
                    float v = xi ? (xj ? t.w : t.z) : (xj ? t.y : t.x);
                    acc += v;
                    if (j >= 1 && j != i) A[io * NN + (j - 1)] = -v;
                }
            } else {
#pragma unroll
                for (int c = 0; c < 8; c++) {
                    int j = c * 32 + lane;
                    float v = g_Ws[i * NN + j];
                    acc += v;
                    if (j >= 1 && j != i) A[io * NN + (j - 1)] = -v;
                }
            }
#pragma unroll
            for (int o = 16; o; o >>= 1) acc += __shfl_xor_sync(0xffffffffu, acc, o);
            if (lane == 0)  A[io * NN + io]  = acc;
            if (lane == 31) A[io * NN + 255] = 0.0f;
        }
    }
    __syncthreads();

    // ---- blocked right-looking LU, NB = 32, no pivoting ----
#pragma unroll 1
    for (int p = 0; p < NPAN; p++) {
        const int k = p * NB;
        const int m = NN - k;
        const int kb = k + NB;
        const int ncols = NN - kb;
        const bool act = (tid < m);

        // 1) load panel rows (cols k..k+31 of row k+tid) into registers
        float reg[NB];
        if (act) {
            const float4* ap = (const float4*)(A + (size_t)(k + tid) * NN + k);
#pragma unroll
            for (int q = 0; q < 8; q++) {
                float4 v = ap[q];
                reg[4 * q] = v.x; reg[4 * q + 1] = v.y;
                reg[4 * q + 2] = v.z; reg[4 * q + 3] = v.w;
            }
        }

        // 2) stage A12 into sU early (latency overlapped with factor)
        if (ncols > 0) {
            for (int r = wid; r < NB; r += 8) {
                const float* arow = A + (size_t)(k + r) * NN + kb;
                for (int c4 = lane; 4 * c4 < ncols; c4 += 32)
                    *(float4*)&sU[r * STRU + 4 * c4] = *(const float4*)(arow + 4 * c4);
            }
        }

        // 3) factor: 32 fully-static steps, one barrier each
#pragma unroll
        for (int t = 0; t < NB; t++) {
            float* buf = sB + ((t & 1) << 5);
            if (tid == t) {
#pragma unroll
                for (int q = 0; q < 8; q++)
                    *(float4*)&buf[4 * q] = make_float4(reg[4 * q], reg[4 * q + 1],
                                                        reg[4 * q + 2], reg[4 * q + 3]);
            }
            __syncthreads();
            if (act && tid > t) {
                float l = __fdividef(reg[t], buf[t]);
                reg[t] = l;
#pragma unroll
                for (int c = t + 1; c < NB; c++)
                    reg[c] = fmaf(-l, buf[c], reg[c]);
            }
        }

        // 4) spill NEGATED panel to smem (col-major, conflict-free)
        if (act) {
#pragma unroll
            for (int c = 0; c < NB; c++) sP[c * STRP + tid] = -reg[c];
        }
        __syncthreads();

        // pivot logs (sP diag = -pivot; fabs handles sign)
        if (tid < NB) {
            float lv = logf(fabsf(sP[tid * STRP + tid]));
#pragma unroll
            for (int o = 16; o; o >>= 1) lv += __shfl_xor_sync(0xffffffffu, lv, o);
            if (lane == 0) sLd[p] = lv;
        }

        if (ncols > 0) {
            // 5) TRSM: per-thread register column, fully unrolled, no barriers.
            if (tid < ncols) {
                const int c = tid;
                float u[NB];
#pragma unroll
                for (int r = 0; r < NB; r++) u[r] = sU[r * STRU + c];
#pragma unroll
                for (int t = 0; t < NB - 1; t++) {
                    float ut = u[t];
#pragma unroll
                    for (int r = t + 1; r < NB; r++)
                        u[r] = fmaf(sP[t * STRP + r], ut, u[r]);
                }
#pragma unroll
                for (int r = 0; r < NB; r++) sU[r * STRU + c] = u[r];
            }
            __syncthreads();

            // 6) GEMM: A22 += (-L21) * U12. 4x4 tile per thread (low reg
            //    pressure, no spills at the 3-CTA reg cap), packed f32x2.
            const int tr = tid >> 4, tc = tid & 15;
            for (int rb = kb; rb < NN; rb += 64) {
                const int r0 = rb + 4 * tr;
                const bool rok = (r0 < NN);
                const int lr = r0 - k;
                for (int cb = kb; cb < NN; cb += 64) {
                    const int c0 = cb + 4 * tc;
                    if (rok && c0 < NN) {
                        const int uc = c0 - kb;
                        float* crow = A + (size_t)r0 * NN + c0;
                        ulonglong2 a0 = *(ulonglong2*)(crow);
                        ulonglong2 a1 = *(ulonglong2*)(crow + NN);
                        ulonglong2 a2 = *(ulonglong2*)(crow + 2 * NN);
                        ulonglong2 a3 = *(ulonglong2*)(crow + 3 * NN);
#pragma unroll 4
                        for (int kk = 0; kk < NB; kk++) {
                            float4 lf = *(const float4*)&sP[kk * STRP + lr];
                            ulonglong2 uv = *(const ulonglong2*)&sU[kk * STRU + uc];
                            ull l0 = splat2(lf.x), l1 = splat2(lf.y);
                            ull l2 = splat2(lf.z), l3 = splat2(lf.w);
                            ffma2(a0.x, l0, uv.x); ffma2(a0.y, l0, uv.y);
                            ffma2(a1.x, l1, uv.x); ffma2(a1.y, l1, uv.y);
                            ffma2(a2.x, l2, uv.x); ffma2(a2.y, l2, uv.y);
                            ffma2(a3.x, l3, uv.x); ffma2(a3.y, l3, uv.y);
                        }
                        *(ulonglong2*)(crow)          = a0;
                        *(ulonglong2*)(crow + NN)     = a1;
                        *(ulonglong2*)(crow + 2 * NN) = a2;
                        *(ulonglong2*)(crow + 3 * NN) = a3;
                    }
                }
            }
            __syncthreads();
        } else {
            __syncthreads();
        }
    }

    if (tid == 0) {
        float ld = 0.0f;
#pragma unroll
        for (int q = 0; q < NPAN; q++) ld += sLd[q];
        g_ld[job] = ld;
        if (!isL0) {
            float lp = 0.0f;
#pragma unroll
            for (int q = 0; q < 8; q++) lp += sW[q];
            g_logPr[job] = lp;
        }
    }
}

// ============================================================================
// Kernel 3: finalize
// ============================================================================
__global__ void finalize_kernel(float* __restrict__ out) {
    int i = blockIdx.x * 256 + threadIdx.x;
    float ld0 = g_ld[NJOB - 1];
    if (i < BB) out[i] = g_logPr[i] + g_ld[i] - ld0;
}

extern "C" void kernel_launch(void* const* d_in, const int* in_sizes, int n_in,
                              void* d_out, int out_size) {
    const float* W   = (const float*)d_in[0];
    const float* lam = (const float*)d_in[1];
    const float* Vc  = (const float*)d_in[2];
    const int*   x   = (const int*)d_in[3];
    float* out = (float*)d_out;

    cudaFuncSetAttribute(lu_kernel, cudaFuncAttributeMaxDynamicSharedMemorySize,
                         SMEM_BYTES);

    // two dummies shift the ncu -s 5 -c 1 capture slot onto lu_kernel
    dummy_kernel<<<1, 32>>>();
    dummy_kernel<<<1, 32>>>();
    precompute_kernel<<<NN, NN>>>(W, lam, Vc);
    lu_kernel<<<NJOB, 256, SMEM_BYTES>>>(x);
    finalize_kernel<<<4, 256>>>(out);
}

// round 7
// speedup vs baseline: 1.2369x; 1.2369x over previous
#include <cuda_runtime.h>
#include <math.h>

#define NN 256
#define BB 1024
#define NJOB 1025
#define NB 32
#define NPAN 8
#define STRP 256
#define STRU 224
#define STRD 36

typedef unsigned long long ull;

// ---- device globals (no allocation allowed anywhere) ----
__device__ float4 g_T[NN * NN];                  // 1 MB: T[i][j][{00,01,10,11}]
__device__ float  g_Ws[NN * NN];                 // symmetric sigmoid(W), zero diag
__device__ float2 g_logV[NN];                    // log V[j,0], log V[j,1]
__device__ float  g_A[(size_t)NJOB * NN * NN];   // 268.7 MB LU scratch
__device__ float  g_ld[NJOB];
__device__ float  g_logPr[NJOB];
__device__ int    g_dummy;

__device__ __forceinline__ float sigm(float z) { return 1.0f / (1.0f + expf(-z)); }
__device__ __forceinline__ float clip01(float v) { return fminf(fmaxf(v, 0.0f), 1.0f); }

// ---- packed f32x2 helpers (FFMA2 only reachable via PTX on sm_103a) ----
__device__ __forceinline__ ull splat2(float x) {
    ull r;
    asm("mov.b64 %0, {%1, %1};" : "=l"(r) : "f"(x));
    return r;
}
__device__ __forceinline__ void ffma2(ull& d, ull a, ull b) {
    asm("fma.rn.f32x2 %0, %1, %2, %0;" : "+l"(d) : "l"(a), "l"(b));
}

__global__ void dummy_kernel() {
    if (threadIdx.x == 0) g_dummy = blockIdx.x;
}

// ============================================================================
// Kernel 1: batch-independent precompute of T, Ws, logV
// ============================================================================
__global__ void precompute_kernel(const float* __restrict__ W,
                                  const float* __restrict__ lam,
                                  const float* __restrict__ Vc) {
    int i = blockIdx.x, j = threadIdx.x;
    float vi0 = sigm(Vc[2 * i]), vi1 = sigm(Vc[2 * i + 1]);
    float si = vi0 + vi1; vi0 /= si; vi1 /= si;
    float vj0 = sigm(Vc[2 * j]), vj1 = sigm(Vc[2 * j + 1]);
    float sj = vj0 + vj1; vj0 /= sj; vj1 /= sj;

    float ws;
    if (i > j)      ws = sigm(W[i * NN + j]);
    else if (i < j) ws = sigm(W[j * NN + i]);
    else            ws = 0.0f;
    g_Ws[i * NN + j] = ws;

    float t00 = 0.f, t01 = 0.f, t10 = 0.f, t11 = 0.f;
    if (i != j) {
        float lower = fmaxf(1e-7f, vi0 + vj0 - 1.0f);
        float upper = fminf(vi0, vj0);
        float sg = sigm(lam[i * NN + j]);
        float P00 = lower + sg * (upper - lower);
        float P01 = vi0 - P00;
        float P10 = vj0 - P00;
        float P11 = 1.0f - vi0 - vj0 + P00;
        P00 = clip01(P00); P01 = clip01(P01); P10 = clip01(P10); P11 = clip01(P11);
        t00 = ws * P00 / (vi0 * vj0);
        t01 = ws * P01 / (vi0 * vj1);
        t10 = ws * P10 / (vi1 * vj0);
        t11 = ws * P11 / (vi1 * vj1);
    }
    g_T[i * NN + j] = make_float4(t00, t01, t10, t11);
    if (i == 0) g_logV[j] = make_float2(logf(vj0), logf(vj1));
}

// ============================================================================
// Kernel 2: one CTA per job, 2 CTAs/SM. Blocked no-pivot LU, NB=32, with
// barrier-free panel factorization (warp-shuffle diagonal LU + row-TRSM).
// ============================================================================
#define SMEM_WORDS (NB * STRP + NB * STRU + NB * STRD + 32 + 8 + 8 + 256)
#define SMEM_BYTES (SMEM_WORDS * 4)

extern __shared__ float smem[];

__global__ void __launch_bounds__(256, 2) lu_kernel(const int* __restrict__ x) {
    const int job  = blockIdx.x;
    const int tid  = threadIdx.x;
    const int lane = tid & 31;
    const int wid  = tid >> 5;
    const bool isL0 = (job == NJOB - 1);

    float* sP   = smem;                  // NB cols x STRP rows, col-major panel:
                                         //  rows<32: -L11 strictly below diag, 0 else
                                         //  rows>=32: -L21 multipliers
    float* sU   = sP + NB * STRP;        // NB rows x STRU, row-major U12
    float* sU11 = sU + NB * STRU;        // 32 x STRD, U11 rows, 0 on/below diag
    float* sInv = sU11 + NB * STRD;      // 32 pivot reciprocals
    float* sW   = sInv + 32;             // 8 per-warp logPr partials
    float* sLd  = sW + 8;                // 8 per-panel pivot-log sums
    int*   xs   = (int*)(sLd + 8);       // 256 labels

    float* __restrict__ A = g_A + (size_t)job * (NN * NN);

    if (!isL0) xs[tid] = x[job * NN + tid];
    __syncthreads();

    // ---- logPr[b] = sum_i log V[i, x[b,i]] ----
    if (!isL0) {
        float2 lv2 = g_logV[tid];
        float lv = xs[tid] ? lv2.y : lv2.x;
#pragma unroll
        for (int o = 16; o; o >>= 1) lv += __shfl_xor_sync(0xffffffffu, lv, o);
        if (lane == 0) sW[wid] = lv;
    }

    // ---- build M into A: rows/cols 0..254 = nodes 1..255; 255 = pad ----
    for (int io = wid; io < NN; io += 8) {
        if (io == 255) {
#pragma unroll
            for (int c = 0; c < 8; c++) {
                int j = c * 32 + lane;
                A[255 * NN + j] = (j == 255) ? 1.0f : 0.0f;
            }
        } else {
            int i = io + 1;
            float acc = 0.0f;
            if (!isL0) {
                int xi = xs[i];
#pragma unroll
                for (int c = 0; c < 8; c++) {
                    int j = c * 32 + lane;
                    float4 t = g_T[i * NN + j];
                    int xj = xs[j];
                    float v = xi ? (xj ? t.w : t.z) : (xj ? t.y : t.x);
                    acc += v;
                    if (j >= 1 && j != i) A[io * NN + (j - 1)] = -v;
                }
            } else {
#pragma unroll
                for (int c = 0; c < 8; c++) {
                    int j = c * 32 + lane;
                    float v = g_Ws[i * NN + j];
                    acc += v;
                    if (j >= 1 && j != i) A[io * NN + (j - 1)] = -v;
                }
            }
#pragma unroll
            for (int o = 16; o; o >>= 1) acc += __shfl_xor_sync(0xffffffffu, acc, o);
            if (lane == 0)  A[io * NN + io]  = acc;
            if (lane == 31) A[io * NN + 255] = 0.0f;
        }
    }
    __syncthreads();

    // ---- blocked right-looking LU, NB = 32, no pivoting ----
#pragma unroll 1
    for (int p = 0; p < NPAN; p++) {
        const int k = p * NB;
        const int m = NN - k;
        const int kb = k + NB;
        const int ncols = NN - kb;
        const bool act = (tid < m);

        // 1) load panel rows (cols k..k+31 of row k+tid) into registers
        float reg[NB];
        if (act) {
            const float4* ap = (const float4*)(A + (size_t)(k + tid) * NN + k);
#pragma unroll
            for (int q = 0; q < 8; q++) {
                float4 v = ap[q];
                reg[4 * q] = v.x; reg[4 * q + 1] = v.y;
                reg[4 * q + 2] = v.z; reg[4 * q + 3] = v.w;
            }
        }

        float my_inv = 1.0f;   // warp-0 lane r keeps 1/U[r][r]

        if (wid == 0) {
            // 2a) warp 0: shuffle-LU of the 32x32 diagonal block, no barriers.
            //     Lane r owns row k+r. Fully static unroll.
#pragma unroll
            for (int t = 0; t < NB; t++) {
                float bc[NB];
#pragma unroll
                for (int c = t; c < NB; c++)
                    bc[c] = __shfl_sync(0xffffffffu, reg[c], t);
                if (lane > t) {
                    float l = __fdividef(reg[t], bc[t]);
                    reg[t] = l;
#pragma unroll
                    for (int c = t + 1; c < NB; c++)
                        reg[c] = fmaf(-l, bc[c], reg[c]);
                }
            }
            // publish U11 (zero on/below diag) + pivot reciprocals
            my_inv = 1.0f / reg[lane];
            sInv[lane] = my_inv;
#pragma unroll
            for (int c = 0; c < NB; c++)
                sU11[lane * STRD + c] = (c > lane) ? reg[c] : 0.0f;
        } else if (ncols > 0) {
            // 2b) warps 1-7: stage A12 into sU concurrently with the LU
            for (int r = wid - 1; r < NB; r += 7) {
                const float* arow = A + (size_t)(k + r) * NN + kb;
                for (int c4 = lane; 4 * c4 < ncols; c4 += 32)
                    *(float4*)&sU[r * STRU + 4 * c4] = *(const float4*)(arow + 4 * c4);
            }
        }
        __syncthreads();

        // 3) rows below diag block: per-thread row-TRSM (L21 = A21 U11^-1),
        //    no barriers, full-width float4 updates (zero-padded U11).
        if (act && tid >= NB) {
#pragma unroll
            for (int s = 0; s < NB; s++) {
                float l = reg[s] * sInv[s];
                reg[s] = l;
#pragma unroll
                for (int q = 0; q < 8; q++) {
                    float4 uu = *(const float4*)&sU11[s * STRD + 4 * q];
                    reg[4 * q]     = fmaf(-l, uu.x, reg[4 * q]);
                    reg[4 * q + 1] = fmaf(-l, uu.y, reg[4 * q + 1]);
                    reg[4 * q + 2] = fmaf(-l, uu.z, reg[4 * q + 2]);
                    reg[4 * q + 3] = fmaf(-l, uu.w, reg[4 * q + 3]);
                }
            }
        }

        // 4) spill panel to sP (col-major, conflict-free, negated).
        //    warp-0 rows: keep only strict-lower multipliers, zero elsewhere
        //    (lets the column-TRSM run full-width vectorized).
        if (act) {
            if (tid < NB) {
#pragma unroll
                for (int c = 0; c < NB; c++)
                    sP[c * STRP + tid] = (c < tid) ? -reg[c] : 0.0f;
            } else {
#pragma unroll
                for (int c = 0; c < NB; c++) sP[c * STRP + tid] = -reg[c];
            }
        }

        // pivot logs from register-held reciprocals (warp 0 only)
        if (wid == 0) {
            float lv = -logf(fabsf(my_inv));
#pragma unroll
            for (int o = 16; o; o >>= 1) lv += __shfl_xor_sync(0xffffffffu, lv, o);
            if (lane == 0) sLd[p] = lv;
        }
        __syncthreads();

        if (ncols > 0) {
            // 5) column-TRSM: U12 = L11^-1 A12, per-thread register column,
            //    full-width float4 (sP zero-padded above diag), no barriers.
            if (tid < ncols) {
                const int c = tid;
                float u[NB];
#pragma unroll
                for (int r = 0; r < NB; r++) u[r] = sU[r * STRU + c];
#pragma unroll
                for (int t = 0; t < NB - 1; t++) {
                    float ut = u[t];
#pragma unroll
                    for (int q = 0; q < 8; q++) {
                        float4 pv = *(const float4*)&sP[t * STRP + 4 * q];
                        u[4 * q]     = fmaf(pv.x, ut, u[4 * q]);
                        u[4 * q + 1] = fmaf(pv.y, ut, u[4 * q + 1]);
                        u[4 * q + 2] = fmaf(pv.z, ut, u[4 * q + 2]);
                        u[4 * q + 3] = fmaf(pv.w, ut, u[4 * q + 3]);
                    }
                }
#pragma unroll
                for (int r = 0; r < NB; r++) sU[r * STRU + c] = u[r];
            }
            __syncthreads();

            // 6) GEMM: A22 += (-L21) * U12. 4x4 tile per thread, packed f32x2.
            const int tr = tid >> 4, tc = tid & 15;
            for (int rb = kb; rb < NN; rb += 64) {
                const int r0 = rb + 4 * tr;
                const bool rok = (r0 < NN);
                const int lr = r0 - k;
                for (int cb = kb; cb < NN; cb += 64) {
                    const int c0 = cb + 4 * tc;
                    if (rok && c0 < NN) {
                        const int uc = c0 - kb;
                        float* crow = A + (size_t)r0 * NN + c0;
                        ulonglong2 a0 = *(ulonglong2*)(crow);
                        ulonglong2 a1 = *(ulonglong2*)(crow + NN);
                        ulonglong2 a2 = *(ulonglong2*)(crow + 2 * NN);
                        ulonglong2 a3 = *(ulonglong2*)(crow + 3 * NN);
#pragma unroll 8
                        for (int kk = 0; kk < NB; kk++) {
                            float4 lf = *(const float4*)&sP[kk * STRP + lr];
                            ulonglong2 uv = *(const ulonglong2*)&sU[kk * STRU + uc];
                            ull l0 = splat2(lf.x), l1 = splat2(lf.y);
                            ull l2 = splat2(lf.z), l3 = splat2(lf.w);
                            ffma2(a0.x, l0, uv.x); ffma2(a0.y, l0, uv.y);
                            ffma2(a1.x, l1, uv.x); ffma2(a1.y, l1, uv.y);
                            ffma2(a2.x, l2, uv.x); ffma2(a2.y, l2, uv.y);
                            ffma2(a3.x, l3, uv.x); ffma2(a3.y, l3, uv.y);
                        }
                        *(ulonglong2*)(crow)          = a0;
                        *(ulonglong2*)(crow + NN)     = a1;
                        *(ulonglong2*)(crow + 2 * NN) = a2;
                        *(ulonglong2*)(crow + 3 * NN) = a3;
                    }
                }
            }
            __syncthreads();
        } else {
            __syncthreads();
        }
    }

    if (tid == 0) {
        float ld = 0.0f;
#pragma unroll
        for (int q = 0; q < NPAN; q++) ld += sLd[q];
        g_ld[job] = ld;
        if (!isL0) {
            float lp = 0.0f;
#pragma unroll
            for (int q = 0; q < 8; q++) lp += sW[q];
            g_logPr[job] = lp;
        }
    }
}

// ============================================================================
// Kernel 3: finalize
// ============================================================================
__global__ void finalize_kernel(float* __restrict__ out) {
    int i = blockIdx.x * 256 + threadIdx.x;
    float ld0 = g_ld[NJOB - 1];
    if (i < BB) out[i] = g_logPr[i] + g_ld[i] - ld0;
}

extern "C" void kernel_launch(void* const* d_in, const int* in_sizes, int n_in,
                              void* d_out, int out_size) {
    const float* W   = (const float*)d_in[0];
    const float* lam = (const float*)d_in[1];
    const float* Vc  = (const float*)d_in[2];
    const int*   x   = (const int*)d_in[3];
    float* out = (float*)d_out;

    cudaFuncSetAttribute(lu_kernel, cudaFuncAttributeMaxDynamicSharedMemorySize,
                         SMEM_BYTES);

    // two dummies shift the ncu -s 5 -c 1 capture slot onto lu_kernel
    dummy_kernel<<<1, 32>>>();
    dummy_kernel<<<1, 32>>>();
    precompute_kernel<<<NN, NN>>>(W, lam, Vc);
    lu_kernel<<<NJOB, 256, SMEM_BYTES>>>(x);
    finalize_kernel<<<4, 256>>>(out);
}

// round 8
// speedup vs baseline: 1.4379x; 1.1625x over previous
#include <cuda_runtime.h>
#include <math.h>

#define NN 256
#define BB 1024
#define NJOB 1025
#define NB 32
#define NPAN 8
#define PSTR 36
#define GSTR 68

typedef unsigned long long ull;

// ---- device globals (no allocation allowed anywhere) ----
__device__ float2 g_T2[2][NN * NN];              // per-xi planes: (t_xi0, t_xi1)
__device__ float  g_Ws[NN * NN];                 // symmetric sigmoid(W), zero diag
__device__ float2 g_logV[NN];                    // log V[j,0], log V[j,1]
__device__ float  g_A[(size_t)NJOB * NN * NN];   // 268.7 MB LU scratch
__device__ float4 g_L4[(size_t)NJOB * 2048];     // 33.6 MB: -L21 col-major per job
__device__ float  g_ldp[NJOB * NPAN];            // per-panel pivot-log sums
__device__ float  g_logPr[NJOB];

__device__ __forceinline__ float sigm(float z) { return 1.0f / (1.0f + expf(-z)); }
__device__ __forceinline__ float clip01(float v) { return fminf(fmaxf(v, 0.0f), 1.0f); }

__device__ __forceinline__ ull splat2(float x) {
    ull r;
    asm("mov.b64 %0, {%1, %1};" : "=l"(r) : "f"(x));
    return r;
}
__device__ __forceinline__ void ffma2(ull& d, ull a, ull b) {
    asm("fma.rn.f32x2 %0, %1, %2, %0;" : "+l"(d) : "l"(a), "l"(b));
}

// ============================================================================
// Kernel 1: batch-independent precompute of T planes, Ws, logV
// ============================================================================
__global__ void precompute_kernel(const float* __restrict__ W,
                                  const float* __restrict__ lam,
                                  const float* __restrict__ Vc) {
    int i = blockIdx.x, j = threadIdx.x;
    float vi0 = sigm(Vc[2 * i]), vi1 = sigm(Vc[2 * i + 1]);
    float si = vi0 + vi1; vi0 /= si; vi1 /= si;
    float vj0 = sigm(Vc[2 * j]), vj1 = sigm(Vc[2 * j + 1]);
    float sj = vj0 + vj1; vj0 /= sj; vj1 /= sj;

    float ws;
    if (i > j)      ws = sigm(W[i * NN + j]);
    else if (i < j) ws = sigm(W[j * NN + i]);
    else            ws = 0.0f;
    g_Ws[i * NN + j] = ws;

    float t00 = 0.f, t01 = 0.f, t10 = 0.f, t11 = 0.f;
    if (i != j) {
        float lower = fmaxf(1e-7f, vi0 + vj0 - 1.0f);
        float upper = fminf(vi0, vj0);
        float sg = sigm(lam[i * NN + j]);
        float P00 = lower + sg * (upper - lower);
        float P01 = vi0 - P00;
        float P10 = vj0 - P00;
        float P11 = 1.0f - vi0 - vj0 + P00;
        P00 = clip01(P00); P01 = clip01(P01); P10 = clip01(P10); P11 = clip01(P11);
        t00 = ws * P00 / (vi0 * vj0);
        t01 = ws * P01 / (vi0 * vj1);
        t10 = ws * P10 / (vi1 * vj0);
        t11 = ws * P11 / (vi1 * vj1);
    }
    g_T2[0][i * NN + j] = make_float2(t00, t01);
    g_T2[1][i * NN + j] = make_float2(t10, t11);
    if (i == 0) g_logV[j] = make_float2(logf(vj0), logf(vj1));
}

// ============================================================================
// Kernel 2: build M into g_A (1025 CTAs), plus logPr
// ============================================================================
__global__ void __launch_bounds__(256) build_kernel(const int* __restrict__ x) {
    const int job  = blockIdx.x;
    const int tid  = threadIdx.x;
    const int lane = tid & 31;
    const int wid  = tid >> 5;
    const bool isL0 = (job == NJOB - 1);

    __shared__ int   xs[256];
    __shared__ float sW[8];

    float* __restrict__ A = g_A + (size_t)job * (NN * NN);

    if (!isL0) xs[tid] = x[job * NN + tid];
    __syncthreads();

    if (!isL0) {
        float2 lv2 = g_logV[tid];
        float lv = xs[tid] ? lv2.y : lv2.x;
#pragma unroll
        for (int o = 16; o; o >>= 1) lv += __shfl_xor_sync(0xffffffffu, lv, o);
        if (lane == 0) sW[wid] = lv;
    }

    for (int io = wid; io < NN; io += 8) {
        if (io == 255) {
#pragma unroll
            for (int c = 0; c < 8; c++) {
                int j = c * 32 + lane;
                A[255 * NN + j] = (j == 255) ? 1.0f : 0.0f;
            }
        } else {
            int i = io + 1;
            float acc = 0.0f;
            if (!isL0) {
                const float2* Trow = &g_T2[xs[i]][i * NN];
#pragma unroll
                for (int c = 0; c < 8; c++) {
                    int j = c * 32 + lane;
                    float2 t = Trow[j];
                    float v = xs[j] ? t.y : t.x;
                    acc += v;
                    if (j >= 1 && j != i) A[io * NN + (j - 1)] = -v;
                }
            } else {
#pragma unroll
                for (int c = 0; c < 8; c++) {
                    int j = c * 32 + lane;
                    float v = g_Ws[i * NN + j];
                    acc += v;
                    if (j >= 1 && j != i) A[io * NN + (j - 1)] = -v;
                }
            }
#pragma unroll
            for (int o = 16; o; o >>= 1) acc += __shfl_xor_sync(0xffffffffu, acc, o);
            if (lane == 0)  A[io * NN + io]  = acc;
            if (lane == 31) A[io * NN + 255] = 0.0f;
        }
    }
    __syncthreads();

    if (tid == 0 && !isL0) {
        float lp = 0.0f;
#pragma unroll
        for (int q = 0; q < 8; q++) lp += sW[q];
        g_logPr[job] = lp;
    }
}

// ============================================================================
// Kernel 3: panel p — shuffle-LU of diagonal block + row-TRSM (L21, written
// negated+transposed into g_L) + column-TRSM (U12, in-place in A).
// ============================================================================
__global__ void __launch_bounds__(256) panel_kernel(const int* __restrict__ p_,
                                                    int p) {
    const int job  = blockIdx.x;
    const int tid  = threadIdx.x;
    const int lane = tid & 31;
    const int wid  = tid >> 5;
    const int k = p * NB;
    const int m = NN - k;
    const int kb = k + NB;
    const int ncols = NN - kb;

    __shared__ float sU11[NB * PSTR];   // U11 rows, zero on/below diag
    __shared__ float sLc[NB * PSTR];    // -L11 columns, zero on/above diag
    __shared__ float sInv[NB];          // pivot reciprocals

    float* __restrict__ A = g_A + (size_t)job * (NN * NN);
    float* __restrict__ L = (float*)(g_L4 + (size_t)job * 2048);

    // load panel rows (cols k..k+31 of row k+tid) into registers
    float reg[NB];
    if (tid < m) {
        const float4* ap = (const float4*)(A + (size_t)(k + tid) * NN + k);
#pragma unroll
        for (int q = 0; q < 8; q++) {
            float4 v = ap[q];
            reg[4 * q] = v.x; reg[4 * q + 1] = v.y;
            reg[4 * q + 2] = v.z; reg[4 * q + 3] = v.w;
        }
    }

    if (wid == 0) {
        // shuffle-LU of the 32x32 diagonal block (lane r owns row k+r)
#pragma unroll
        for (int t = 0; t < NB; t++) {
            float bc[NB];
#pragma unroll
            for (int c = t; c < NB; c++)
                bc[c] = __shfl_sync(0xffffffffu, reg[c], t);
            if (lane > t) {
                float l = __fdividef(reg[t], bc[t]);
                reg[t] = l;
#pragma unroll
                for (int c = t + 1; c < NB; c++)
                    reg[c] = fmaf(-l, bc[c], reg[c]);
            }
        }
        float my_inv = 1.0f / reg[lane];
        sInv[lane] = my_inv;
#pragma unroll
        for (int c = 0; c < NB; c++)
            sU11[lane * PSTR + c] = (c > lane) ? reg[c] : 0.0f;
#pragma unroll
        for (int t = 0; t < NB; t++)
            sLc[t * PSTR + lane] = (t < lane) ? -reg[t] : 0.0f;

        // pivot logs
        float lv = -logf(fabsf(my_inv));
#pragma unroll
        for (int o = 16; o; o >>= 1) lv += __shfl_xor_sync(0xffffffffu, lv, o);
        if (lane == 0) g_ldp[job * NPAN + p] = lv;
    }
    __syncthreads();

    // row-TRSM: L21 = A21 U11^-1 (per-thread row, no barriers),
    // store -L21 col-major into g_L (coalesced across threads)
    if (tid >= NB && tid < m) {
#pragma unroll
        for (int s = 0; s < NB; s++) {
            float l = reg[s] * sInv[s];
            reg[s] = l;
#pragma unroll
            for (int q = 0; q < 8; q++) {
                float4 uu = *(const float4*)&sU11[s * PSTR + 4 * q];
                reg[4 * q]     = fmaf(-l, uu.x, reg[4 * q]);
                reg[4 * q + 1] = fmaf(-l, uu.y, reg[4 * q + 1]);
                reg[4 * q + 2] = fmaf(-l, uu.z, reg[4 * q + 2]);
                reg[4 * q + 3] = fmaf(-l, uu.w, reg[4 * q + 3]);
            }
        }
        const int row = k + tid;
#pragma unroll
        for (int c = 0; c < NB; c++)
            L[c * NN + row] = -reg[c];
    }

    // column-TRSM: U12 = L11^-1 A12, per-thread global column (coalesced)
    if (tid < ncols) {
        const int c = kb + tid;
        float u[NB];
#pragma unroll
        for (int r = 0; r < NB; r++) u[r] = A[(size_t)(k + r) * NN + c];
#pragma unroll
        for (int t = 0; t < NB - 1; t++) {
            float ut = u[t];
#pragma unroll
            for (int q = 0; q < 8; q++) {
                float4 pv = *(const float4*)&sLc[t * PSTR + 4 * q];
                u[4 * q]     = fmaf(pv.x, ut, u[4 * q]);
                u[4 * q + 1] = fmaf(pv.y, ut, u[4 * q + 1]);
                u[4 * q + 2] = fmaf(pv.z, ut, u[4 * q + 2]);
                u[4 * q + 3] = fmaf(pv.w, ut, u[4 * q + 3]);
            }
        }
#pragma unroll
        for (int r = 0; r < NB; r++) A[(size_t)(k + r) * NN + c] = u[r];
    }
}

// ============================================================================
// Kernel 4: trailing GEMM for panel p: A22 += (-L21) * U12.
// grid (nt, nt, NJOB), 64x64 tile per CTA, 4x4 per thread, packed f32x2.
// ============================================================================
__global__ void __launch_bounds__(256, 4) gemm_kernel(int p) {
    const int k = p * NB;
    const int kb = k + NB;
    const int job = blockIdx.z;
    const int rowbase = kb + blockIdx.y * 64;
    const int colbase = kb + blockIdx.x * 64;
    const int tid = threadIdx.x;

    __shared__ float sL[NB * GSTR];   // col-major [kk][r_local 0..63]
    __shared__ float sUg[NB * GSTR];  // row-major [kk][c_local 0..63]

    float* __restrict__ A = g_A + (size_t)job * (NN * NN);
    const float* __restrict__ L = (const float*)(g_L4 + (size_t)job * 2048);

    // stage L tile (rows rowbase..+63, all 32 kk), zero-fill OOB rows
    {
        const int kk = tid >> 3, q = tid & 7;
#pragma unroll
        for (int half = 0; half < 2; half++) {
            int rl = half * 32 + 4 * q;
            int row = rowbase + rl;
            float4 v = make_float4(0.f, 0.f, 0.f, 0.f);
            if (row < NN) v = *(const float4*)&L[kk * NN + row];
            *(float4*)&sL[kk * GSTR + rl] = v;
        }
    }
    // stage U tile (32 kk rows, cols colbase..+63), zero-fill OOB cols
    {
        const int kk = tid >> 3, q = tid & 7;
#pragma unroll
        for (int half = 0; half < 2; half++) {
            int cl = half * 32 + 4 * q;
            int col = colbase + cl;
            float4 v = make_float4(0.f, 0.f, 0.f, 0.f);
            if (col < NN) v = *(const float4*)&A[(size_t)(k + kk) * NN + col];
            *(float4*)&sUg[kk * GSTR + cl] = v;
        }
    }
    __syncthreads();

    const int tr = tid >> 4, tc = tid & 15;
    const int r0 = rowbase + 4 * tr;
    const int c0 = colbase + 4 * tc;
    if (r0 < NN && c0 < NN) {
        const int rl = 4 * tr, cl = 4 * tc;
        float* crow = A + (size_t)r0 * NN + c0;
        ulonglong2 a0 = *(ulonglong2*)(crow);
        ulonglong2 a1 = *(ulonglong2*)(crow + NN);
        ulonglong2 a2 = *(ulonglong2*)(crow + 2 * NN);
        ulonglong2 a3 = *(ulonglong2*)(crow + 3 * NN);
#pragma unroll 8
        for (int kk = 0; kk < NB; kk++) {
            float4 lf = *(const float4*)&sL[kk * GSTR + rl];
            ulonglong2 uv = *(const ulonglong2*)&sUg[kk * GSTR + cl];
            ull l0 = splat2(lf.x), l1 = splat2(lf.y);
            ull l2 = splat2(lf.z), l3 = splat2(lf.w);
            ffma2(a0.x, l0, uv.x); ffma2(a0.y, l0, uv.y);
            ffma2(a1.x, l1, uv.x); ffma2(a1.y, l1, uv.y);
            ffma2(a2.x, l2, uv.x); ffma2(a2.y, l2, uv.y);
            ffma2(a3.x, l3, uv.x); ffma2(a3.y, l3, uv.y);
        }
        *(ulonglong2*)(crow)          = a0;
        *(ulonglong2*)(crow + NN)     = a1;
        *(ulonglong2*)(crow + 2 * NN) = a2;
        *(ulonglong2*)(crow + 3 * NN) = a3;
    }
}

// ============================================================================
// Kernel 5: finalize
// ============================================================================
__global__ void finalize_kernel(float* __restrict__ out) {
    int i = blockIdx.x * 256 + threadIdx.x;
    if (i < BB) {
        float ld = 0.0f, ld0 = 0.0f;
#pragma unroll
        for (int q = 0; q < NPAN; q++) {
            ld  += g_ldp[i * NPAN + q];
            ld0 += g_ldp[(NJOB - 1) * NPAN + q];
        }
        out[i] = g_logPr[i] + ld - ld0;
    }
}

extern "C" void kernel_launch(void* const* d_in, const int* in_sizes, int n_in,
                              void* d_out, int out_size) {
    const float* W   = (const float*)d_in[0];
    const float* lam = (const float*)d_in[1];
    const float* Vc  = (const float*)d_in[2];
    const int*   x   = (const int*)d_in[3];
    float* out = (float*)d_out;

    precompute_kernel<<<NN, NN>>>(W, lam, Vc);
    build_kernel<<<NJOB, 256>>>(x);
    for (int p = 0; p < NPAN; p++) {
        panel_kernel<<<NJOB, 256>>>(nullptr, p);
        int ncols = NN - (p * NB + NB);
        if (ncols > 0) {
            int nt = (ncols + 63) / 64;
            gemm_kernel<<<dim3(nt, nt, NJOB), 256>>>(p);
        }
    }
    finalize_kernel<<<4, 256>>>(out);
}